// round 14
// baseline (speedup 1.0000x reference)
#include <cuda_runtime.h>
#include <cuda_bf16.h>
#include <math.h>

#define EMBED 768
#define HEADS 12
#define HDIM  64
#define BATCH 2
#define SEQ   2048
#define MROWS (BATCH * SEQ)      // 4096
#define BH    (BATCH * HEADS)    // 24
#define NX (MROWS * EMBED)
#define NW (EMBED * EMBED)
#define BHS (BH * SEQ)           // 49152
#define NSPLIT 3
#define QBLKS (SEQ / 128)        // 16

// ---------------- scratch ----------------
__device__ __nv_bfloat16 g_Xhi[NX], g_Xlo[NX];
__device__ __nv_bfloat16 g_W0hi[NW], g_W0lo[NW];
__device__ __nv_bfloat16 g_W1hi[NW], g_W1lo[NW];
__device__ __nv_bfloat16 g_W2hi[NW], g_W2lo[NW];
__device__ __nv_bfloat16 g_W3hi[NW], g_W3lo[NW];
__device__ __nv_bfloat16 g_Qh[NX], g_Ql[NX];
__device__ __nv_bfloat16 g_Kh[NX], g_Kl[NX];
__device__ __nv_bfloat16 g_Vh[NX], g_Vl[NX];
__device__ __nv_bfloat16 g_Ahi[NX], g_Alo[NX];
// split-KV partials + completion tickets
__device__ float g_Op[NSPLIT * BHS * HDIM];
__device__ float g_Mp[NSPLIT * BHS];
__device__ float g_Lp[NSPLIT * BHS];
__device__ unsigned g_cnt[QBLKS * BH];   // zero-init; reset by merging CTA each run

// ---------------- PTX helpers (family-portable sm_80+) ----------------
__device__ __forceinline__ unsigned smem_u32(const void* p) {
    unsigned a;
    asm("{ .reg .u64 t; cvta.to.shared.u64 t, %1; cvt.u32.u64 %0, t; }" : "=r"(a) : "l"(p));
    return a;
}
__device__ __forceinline__ void cp16(unsigned s, const void* g) {
    asm volatile("cp.async.cg.shared.global [%0], [%1], 16;" :: "r"(s), "l"(g));
}
__device__ __forceinline__ void cp_commit() { asm volatile("cp.async.commit_group;" ::: "memory"); }
template <int N> __device__ __forceinline__ void cp_wait() {
    asm volatile("cp.async.wait_group %0;" :: "n"(N) : "memory");
}
__device__ __forceinline__ void ldx4(unsigned* r, unsigned addr) {
    asm volatile("ldmatrix.sync.aligned.m8n8.x4.shared.b16 {%0,%1,%2,%3}, [%4];"
        : "=r"(r[0]), "=r"(r[1]), "=r"(r[2]), "=r"(r[3]) : "r"(addr));
}
__device__ __forceinline__ void ldx4t(unsigned* r, unsigned addr) {
    asm volatile("ldmatrix.sync.aligned.m8n8.x4.trans.shared.b16 {%0,%1,%2,%3}, [%4];"
        : "=r"(r[0]), "=r"(r[1]), "=r"(r[2]), "=r"(r[3]) : "r"(addr));
}
__device__ __forceinline__ void mma16816(float* d, const unsigned* a, const unsigned* b) {
    asm volatile(
        "mma.sync.aligned.m16n8k16.row.col.f32.bf16.bf16.f32 "
        "{%0,%1,%2,%3}, {%4,%5,%6,%7}, {%8,%9}, {%0,%1,%2,%3};"
        : "+f"(d[0]), "+f"(d[1]), "+f"(d[2]), "+f"(d[3])
        : "r"(a[0]), "r"(a[1]), "r"(a[2]), "r"(a[3]), "r"(b[0]), "r"(b[1]));
}
__device__ __forceinline__ unsigned pack_bf2(float a, float b) {
    __nv_bfloat162 t = __float22bfloat162_rn(make_float2(a, b));
    return *(unsigned*)&t;
}
__device__ __forceinline__ unsigned pack_hi_res(float a, float b, float& ra, float& rb) {
    __nv_bfloat162 t = __float22bfloat162_rn(make_float2(a, b));
    ra = a - __bfloat162float(t.x);
    rb = b - __bfloat162float(t.y);
    return *(unsigned*)&t;
}

// ---------------- fused fp32 -> bf16 hi/lo split (all 5 inputs) ----------------
struct alignas(8) B4 { __nv_bfloat16 v[4]; };
#define CONV_TASKS ((NX + 4 * NW) / 8)

__global__ void __launch_bounds__(256)
convert_all_kernel(const float* __restrict__ x,
                   const float* __restrict__ w0, const float* __restrict__ w1,
                   const float* __restrict__ w2, const float* __restrict__ w3,
                   __nv_bfloat16* xh, __nv_bfloat16* xl,
                   __nv_bfloat16* w0h, __nv_bfloat16* w0l,
                   __nv_bfloat16* w1h, __nv_bfloat16* w1l,
                   __nv_bfloat16* w2h, __nv_bfloat16* w2l,
                   __nv_bfloat16* w3h, __nv_bfloat16* w3l)
{
    long long t = (long long)blockIdx.x * 256 + threadIdx.x;
    if (t >= CONV_TASKS) return;
    long long i = t * 8;
    const float* src;
    __nv_bfloat16 *hi, *lo;
    long long off;
    if (i < NX) { src = x; hi = xh; lo = xl; off = i; }
    else {
        long long j = i - NX;
        int w = (int)(j / NW);
        off = j - (long long)w * NW;
        if      (w == 0) { src = w0; hi = w0h; lo = w0l; }
        else if (w == 1) { src = w1; hi = w1h; lo = w1l; }
        else if (w == 2) { src = w2; hi = w2h; lo = w2l; }
        else             { src = w3; hi = w3h; lo = w3l; }
    }
#pragma unroll
    for (int half = 0; half < 2; half++) {
        float4 v = *(const float4*)&src[off + half * 4];
        B4 h, l;
        float f[4] = {v.x, v.y, v.z, v.w};
#pragma unroll
        for (int j = 0; j < 4; j++) {
            h.v[j] = __float2bfloat16(f[j]);
            l.v[j] = __float2bfloat16(f[j] - __bfloat162float(h.v[j]));
        }
        *(B4*)&hi[off + half * 4] = h;
        *(B4*)&lo[off + half * 4] = l;
    }
}

// ---------------- HMMA GEMM body, templated on N tile (bf16x3) ----------------
#define GBM 128
#define GBK 32
#define KITERS (EMBED / GBK)     // 24
#define ASTR 80
#define A_SZ (128 * ASTR)        // 10240

template <int BN>
__device__ __forceinline__ void
gemm_body(unsigned sb,
          const __nv_bfloat16* __restrict__ Ahi, const __nv_bfloat16* __restrict__ Alo,
          const __nv_bfloat16* __restrict__ Bhi, const __nv_bfloat16* __restrict__ Blo,
          const float* __restrict__ bias, float* __restrict__ Yf,
          __nv_bfloat16* __restrict__ Yhi, __nv_bfloat16* __restrict__ Ylo,
          int mode, float scale, int m0, int n0)
{
    constexpr int B_SZ  = BN * ASTR;
    constexpr int STAGE = 2 * A_SZ + 2 * B_SZ;
    constexpr int NT    = BN / 16;
    constexpr int WNSP  = BN / 2;

    const int tid  = threadIdx.x;
    const int lane = tid & 31;
    const int wid  = tid >> 5;
    const int warpM = wid & 3;
    const int warpN = wid >> 2;

    auto sA_hi = [&](int s) { return sb + s * STAGE; };
    auto sA_lo = [&](int s) { return sb + s * STAGE + A_SZ; };
    auto sB_hi = [&](int s) { return sb + s * STAGE + 2 * A_SZ; };
    auto sB_lo = [&](int s) { return sb + s * STAGE + 2 * A_SZ + B_SZ; };

    const int r0_ = (tid * 2) >> 2, c0_ = (tid * 2) & 3;
    const int r1_ = (tid * 2 + 1) >> 2, c1_ = (tid * 2 + 1) & 3;
    const int br = tid >> 2, bc = tid & 3;

    auto load_stage = [&](int kt, int s) {
        const int k0 = kt * GBK;
        const __nv_bfloat16* pah = Ahi + (size_t)m0 * EMBED + k0;
        const __nv_bfloat16* pal = Alo + (size_t)m0 * EMBED + k0;
        const __nv_bfloat16* pbh = Bhi + (size_t)n0 * EMBED + k0;
        const __nv_bfloat16* pbl = Blo + (size_t)n0 * EMBED + k0;
        cp16(sA_hi(s) + r0_ * ASTR + c0_ * 16, pah + (size_t)r0_ * EMBED + c0_ * 8);
        cp16(sA_hi(s) + r1_ * ASTR + c1_ * 16, pah + (size_t)r1_ * EMBED + c1_ * 8);
        cp16(sA_lo(s) + r0_ * ASTR + c0_ * 16, pal + (size_t)r0_ * EMBED + c0_ * 8);
        cp16(sA_lo(s) + r1_ * ASTR + c1_ * 16, pal + (size_t)r1_ * EMBED + c1_ * 8);
        if (BN == 128) {
            cp16(sB_hi(s) + r0_ * ASTR + c0_ * 16, pbh + (size_t)r0_ * EMBED + c0_ * 8);
            cp16(sB_hi(s) + r1_ * ASTR + c1_ * 16, pbh + (size_t)r1_ * EMBED + c1_ * 8);
            cp16(sB_lo(s) + r0_ * ASTR + c0_ * 16, pbl + (size_t)r0_ * EMBED + c0_ * 8);
            cp16(sB_lo(s) + r1_ * ASTR + c1_ * 16, pbl + (size_t)r1_ * EMBED + c1_ * 8);
        } else {
            cp16(sB_hi(s) + br * ASTR + bc * 16, pbh + (size_t)br * EMBED + bc * 8);
            cp16(sB_lo(s) + br * ASTR + bc * 16, pbl + (size_t)br * EMBED + bc * 8);
        }
        cp_commit();
    };

    const unsigned aOff = (unsigned)((warpM * 32 + ((lane >> 3) & 1) * 8 + (lane & 7)) * ASTR
                                     + (lane >> 4) * 16);
    const unsigned bOff = (unsigned)((warpN * WNSP + ((lane >> 4) & 1) * 8 + (lane & 7)) * ASTR
                                     + ((lane >> 3) & 1) * 16);

    float acc[2][NT][4];
#pragma unroll
    for (int mt = 0; mt < 2; mt++)
#pragma unroll
        for (int nt = 0; nt < NT; nt++)
#pragma unroll
            for (int j = 0; j < 4; j++) acc[mt][nt][j] = 0.f;

    load_stage(0, 0);

    for (int kt = 0; kt < KITERS; kt++) {
        const int s = kt & 1;
        cp_wait<0>();
        __syncthreads();
        if (kt + 1 < KITERS) load_stage(kt + 1, s ^ 1);

#pragma unroll
        for (int ks = 0; ks < 2; ks++) {
            unsigned a_h[2][4], a_l[2][4];
#pragma unroll
            for (int mt = 0; mt < 2; mt++) {
                ldx4(a_h[mt], sA_hi(s) + aOff + mt * (16 * ASTR) + ks * 32);
                ldx4(a_l[mt], sA_lo(s) + aOff + mt * (16 * ASTR) + ks * 32);
            }
#pragma unroll
            for (int p = 0; p < NT / 2; p++) {
                unsigned b_h[4], b_l[4];
                ldx4(b_h, sB_hi(s) + bOff + p * (16 * ASTR) + ks * 32);
                ldx4(b_l, sB_lo(s) + bOff + p * (16 * ASTR) + ks * 32);
#pragma unroll
                for (int mt = 0; mt < 2; mt++)
#pragma unroll
                    for (int j = 0; j < 2; j++) {
                        const int nt = p * 2 + j;
                        mma16816(acc[mt][nt], a_h[mt], &b_h[j * 2]);
                        mma16816(acc[mt][nt], a_h[mt], &b_l[j * 2]);
                        mma16816(acc[mt][nt], a_l[mt], &b_h[j * 2]);
                    }
            }
        }
    }

    const int g  = lane >> 2;
    const int tg = lane & 3;
#pragma unroll
    for (int mt = 0; mt < 2; mt++) {
#pragma unroll
        for (int nt = 0; nt < NT; nt++) {
            const int nl = warpN * WNSP + nt * 8 + tg * 2;
            const int n  = n0 + nl;
            float2 bv = *(const float2*)&bias[n];
#pragma unroll
            for (int half = 0; half < 2; half++) {
                const int ml = warpM * 32 + mt * 16 + g + half * 8;
                const int m  = m0 + ml;
                float c0 = acc[mt][nt][half * 2 + 0] + bv.x;
                float c1 = acc[mt][nt][half * 2 + 1] + bv.y;
                if (mode == 0) {
                    const int h = n >> 6;
                    const int bb = m >> 11;
                    const int ss = m & 2047;
                    float v0 = c0 * scale, v1 = c1 * scale;
                    float r0, r1;
                    unsigned hp = pack_hi_res(v0, v1, r0, r1);
                    unsigned lp = pack_bf2(r0, r1);
                    size_t idx = ((size_t)(bb * HEADS + h) * SEQ + ss) * HDIM + (n & 63);
                    *(unsigned*)&Yhi[idx] = hp;
                    *(unsigned*)&Ylo[idx] = lp;
                } else {
                    *(float2*)&Yf[(size_t)m * EMBED + n] = make_float2(c0, c1);
                }
            }
        }
    }
}

#define QKV_BN 128
#define QKV_NBLK (EMBED / QKV_BN)   // 6
#define SMEM_GEMM_QKV (2 * (2 * A_SZ + 2 * QKV_BN * ASTR))   // 81920
#define O_BN 64
#define O_NBLK (EMBED / O_BN)       // 12
#define SMEM_GEMM_O (2 * (2 * A_SZ + 2 * O_BN * ASTR))       // 61440

__global__ void __launch_bounds__(256, 2)
mma_gemm_qkv_kernel(const __nv_bfloat16* __restrict__ xh, const __nv_bfloat16* __restrict__ xl,
                    const __nv_bfloat16* __restrict__ w0h, const __nv_bfloat16* __restrict__ w0l,
                    const __nv_bfloat16* __restrict__ w1h, const __nv_bfloat16* __restrict__ w1l,
                    const __nv_bfloat16* __restrict__ w2h, const __nv_bfloat16* __restrict__ w2l,
                    const float* __restrict__ b_q, const float* __restrict__ b_k,
                    const float* __restrict__ b_v,
                    __nv_bfloat16* qh, __nv_bfloat16* ql,
                    __nv_bfloat16* kh, __nv_bfloat16* kl,
                    __nv_bfloat16* vh, __nv_bfloat16* vl)
{
    extern __shared__ char smraw[];
    const unsigned sb = smem_u32(smraw);
    const int pj   = blockIdx.x / QKV_NBLK;
    const int nblk = blockIdx.x % QKV_NBLK;
    const __nv_bfloat16 *Bh, *Bl;
    const float* bias;
    __nv_bfloat16 *Yh, *Yl;
    float scale;
    if (pj == 0)      { Bh = w0h; Bl = w0l; bias = b_q; Yh = qh; Yl = ql; scale = 0.125f; }
    else if (pj == 1) { Bh = w1h; Bl = w1l; bias = b_k; Yh = kh; Yl = kl; scale = 1.0f; }
    else              { Bh = w2h; Bl = w2l; bias = b_v; Yh = vh; Yl = vl; scale = 1.0f; }
    gemm_body<QKV_BN>(sb, xh, xl, Bh, Bl, bias, nullptr, Yh, Yl, 0, scale,
                      blockIdx.y * GBM, nblk * QKV_BN);
}

__global__ void __launch_bounds__(256, 3)
mma_gemm_o_kernel(const __nv_bfloat16* __restrict__ ah, const __nv_bfloat16* __restrict__ al,
                  const __nv_bfloat16* __restrict__ w3h, const __nv_bfloat16* __restrict__ w3l,
                  const float* __restrict__ b_o, float* __restrict__ out)
{
    extern __shared__ char smraw[];
    const unsigned sb = smem_u32(smraw);
    gemm_body<O_BN>(sb, ah, al, w3h, w3l, b_o, out, nullptr, nullptr, 1, 1.0f,
                    blockIdx.y * GBM, blockIdx.x * O_BN);
}

// ---------------- Flash attention, split-KV x3, fused last-split merge ----------------
#define QSTR 144
#define F_oQh 0
#define F_oQl 18432
#define KV_BASE 36864
#define KV_STAGE 36864
#define KV_oKh 0
#define KV_oKl 9216
#define KV_oVh 18432
#define KV_oVl 27648
#define SMEM_FLASH (KV_BASE + 2 * KV_STAGE)   // 110592

__global__ void __launch_bounds__(256)
flash_mma_kernel(const __nv_bfloat16* __restrict__ Qh, const __nv_bfloat16* __restrict__ Ql,
                 const __nv_bfloat16* __restrict__ Kh, const __nv_bfloat16* __restrict__ Kl,
                 const __nv_bfloat16* __restrict__ Vh, const __nv_bfloat16* __restrict__ Vl,
                 __nv_bfloat16* __restrict__ Ahi, __nv_bfloat16* __restrict__ Alo)
{
    extern __shared__ char smf[];
    __shared__ unsigned s_last;
    const unsigned sb = smem_u32(smf);
    const int tid  = threadIdx.x;
    const int lane = tid & 31;
    const int wid  = tid >> 5;
    const int bh   = blockIdx.y;
    const int q0   = blockIdx.x * 128;
    const int split = blockIdx.z;

    const size_t qoff = ((size_t)bh * SEQ + q0) * HDIM;
    const size_t koff = (size_t)bh * SEQ * HDIM;
    const __nv_bfloat16* pQh = Qh + qoff;
    const __nv_bfloat16* pQl = Ql + qoff;
    const __nv_bfloat16* pKh = Kh + koff;
    const __nv_bfloat16* pKl = Kl + koff;
    const __nv_bfloat16* pVh = Vh + koff;
    const __nv_bfloat16* pVl = Vl + koff;

#pragma unroll
    for (int i = 0; i < 4; i++) {
        int task = tid + i * 256;
        int r = task >> 3, c = task & 7;
        cp16(sb + F_oQh + r * QSTR + c * 16, pQh + (size_t)r * HDIM + c * 8);
        cp16(sb + F_oQl + r * QSTR + c * 16, pQl + (size_t)r * HDIM + c * 8);
    }
    cp_commit();

    auto load_kv = [&](int kt, int s) {
        const unsigned st = sb + KV_BASE + s * KV_STAGE;
        const int k0 = kt * 64;
#pragma unroll
        for (int i = 0; i < 2; i++) {
            int task = tid + i * 256;
            int r = task >> 3, c = task & 7;
            size_t go = (size_t)(k0 + r) * HDIM + c * 8;
            unsigned so = r * QSTR + c * 16;
            cp16(st + KV_oKh + so, pKh + go);
            cp16(st + KV_oKl + so, pKl + go);
            cp16(st + KV_oVh + so, pVh + go);
            cp16(st + KV_oVl + so, pVl + go);
        }
        cp_commit();
    };

    const int g  = lane >> 2;
    const int tg = lane & 3;
    const unsigned aAddr = sb + (unsigned)((wid * 16 + ((lane >> 3) & 1) * 8 + (lane & 7)) * QSTR
                                           + (lane >> 4) * 16);
    const unsigned kRel = (unsigned)((((lane >> 4) & 1) * 8 + (lane & 7)) * QSTR
                                     + ((lane >> 3) & 1) * 16);
    const unsigned vRel = (unsigned)((((lane >> 3) & 1) * 8 + (lane & 7)) * QSTR
                                     + (lane >> 4) * 16);

    float m0 = -INFINITY, m1 = -INFINITY, l0 = 0.f, l1 = 0.f;
    float o[8][4];
#pragma unroll
    for (int nf = 0; nf < 8; nf++)
#pragma unroll
        for (int j = 0; j < 4; j++) o[nf][j] = 0.f;

    const int kt0 = split * 11;
    const int kt1 = (split == 2) ? 32 : kt0 + 11;
    load_kv(kt0, 0);

    for (int kt = kt0; kt < kt1; kt++) {
        const int s = (kt - kt0) & 1;
        cp_wait<0>();
        __syncthreads();
        if (kt + 1 < kt1) load_kv(kt + 1, s ^ 1);

        const unsigned stK = sb + KV_BASE + s * KV_STAGE;

        float sc[8][4];
#pragma unroll
        for (int nf = 0; nf < 8; nf++)
#pragma unroll
            for (int j = 0; j < 4; j++) sc[nf][j] = 0.f;

#pragma unroll
        for (int ks = 0; ks < 4; ks++) {
            unsigned qhf[4], qlf[4];
            ldx4(qhf, aAddr + F_oQh + ks * 32);
            ldx4(qlf, aAddr + F_oQl + ks * 32);
#pragma unroll
            for (int p = 0; p < 4; p++) {
                unsigned khf[4], klf[4];
                ldx4(khf, stK + KV_oKh + kRel + p * (16 * QSTR) + ks * 32);
                ldx4(klf, stK + KV_oKl + kRel + p * (16 * QSTR) + ks * 32);
                mma16816(sc[2 * p],     qhf, &khf[0]);
                mma16816(sc[2 * p],     qhf, &klf[0]);
                mma16816(sc[2 * p],     qlf, &khf[0]);
                mma16816(sc[2 * p + 1], qhf, &khf[2]);
                mma16816(sc[2 * p + 1], qhf, &klf[2]);
                mma16816(sc[2 * p + 1], qlf, &khf[2]);
            }
        }

        float pm0 = sc[0][0], pm1 = sc[0][2];
#pragma unroll
        for (int nf = 0; nf < 8; nf++) {
            pm0 = fmaxf(pm0, fmaxf(sc[nf][0], sc[nf][1]));
            pm1 = fmaxf(pm1, fmaxf(sc[nf][2], sc[nf][3]));
        }
        pm0 = fmaxf(pm0, __shfl_xor_sync(0xffffffffu, pm0, 1, 4));
        pm0 = fmaxf(pm0, __shfl_xor_sync(0xffffffffu, pm0, 2, 4));
        pm1 = fmaxf(pm1, __shfl_xor_sync(0xffffffffu, pm1, 1, 4));
        pm1 = fmaxf(pm1, __shfl_xor_sync(0xffffffffu, pm1, 2, 4));
        const float mn0 = fmaxf(m0, pm0);
        const float mn1 = fmaxf(m1, pm1);
        const float al0 = __expf(m0 - mn0);
        const float al1 = __expf(m1 - mn1);
        m0 = mn0; m1 = mn1;
        float ps0 = 0.f, ps1 = 0.f;
#pragma unroll
        for (int nf = 0; nf < 8; nf++) {
            sc[nf][0] = __expf(sc[nf][0] - mn0);
            sc[nf][1] = __expf(sc[nf][1] - mn0);
            sc[nf][2] = __expf(sc[nf][2] - mn1);
            sc[nf][3] = __expf(sc[nf][3] - mn1);
            ps0 += sc[nf][0] + sc[nf][1];
            ps1 += sc[nf][2] + sc[nf][3];
        }
        ps0 += __shfl_xor_sync(0xffffffffu, ps0, 1, 4);
        ps0 += __shfl_xor_sync(0xffffffffu, ps0, 2, 4);
        ps1 += __shfl_xor_sync(0xffffffffu, ps1, 1, 4);
        ps1 += __shfl_xor_sync(0xffffffffu, ps1, 2, 4);
        l0 = l0 * al0 + ps0;
        l1 = l1 * al1 + ps1;
#pragma unroll
        for (int nf = 0; nf < 8; nf++) {
            o[nf][0] *= al0; o[nf][1] *= al0;
            o[nf][2] *= al1; o[nf][3] *= al1;
        }

#pragma unroll
        for (int kb = 0; kb < 4; kb++) {
            float r0, r1, r2, r3, r4, r5, r6, r7;
            unsigned pa_h[4], pa_l[4];
            pa_h[0] = pack_hi_res(sc[2 * kb][0],     sc[2 * kb][1],     r0, r1);
            pa_h[1] = pack_hi_res(sc[2 * kb][2],     sc[2 * kb][3],     r2, r3);
            pa_h[2] = pack_hi_res(sc[2 * kb + 1][0], sc[2 * kb + 1][1], r4, r5);
            pa_h[3] = pack_hi_res(sc[2 * kb + 1][2], sc[2 * kb + 1][3], r6, r7);
            pa_l[0] = pack_bf2(r0, r1);
            pa_l[1] = pack_bf2(r2, r3);
            pa_l[2] = pack_bf2(r4, r5);
            pa_l[3] = pack_bf2(r6, r7);
#pragma unroll
            for (int du = 0; du < 4; du++) {
                unsigned vhf[4], vlf[4];
                ldx4t(vhf, stK + KV_oVh + vRel + kb * (16 * QSTR) + du * 32);
                ldx4t(vlf, stK + KV_oVl + vRel + kb * (16 * QSTR) + du * 32);
                mma16816(o[du * 2],     pa_h, &vhf[0]);
                mma16816(o[du * 2],     pa_h, &vlf[0]);
                mma16816(o[du * 2],     pa_l, &vhf[0]);
                mma16816(o[du * 2 + 1], pa_h, &vhf[2]);
                mma16816(o[du * 2 + 1], pa_h, &vlf[2]);
                mma16816(o[du * 2 + 1], pa_l, &vhf[2]);
            }
        }
    }

    // ---- store unnormalized partials + (m, l) ----
    const int r0 = q0 + wid * 16 + g;
    const size_t prow = (size_t)(split * BH + bh) * SEQ + r0;
    float* Op0 = &g_Op[prow * HDIM];
    float* Op1 = &g_Op[(prow + 8) * HDIM];
#pragma unroll
    for (int nf = 0; nf < 8; nf++) {
        const int e = nf * 8 + tg * 2;
        *(float2*)&Op0[e] = make_float2(o[nf][0], o[nf][1]);
        *(float2*)&Op1[e] = make_float2(o[nf][2], o[nf][3]);
    }
    if (tg == 0) {
        g_Mp[prow] = m0;     g_Lp[prow] = l0;
        g_Mp[prow + 8] = m1; g_Lp[prow + 8] = l1;
    }

    // ---- last-split-merges ticket ----
    __threadfence();                       // publish this CTA's partials
    __syncthreads();                       // all threads' stores + fences done
    const int slot = blockIdx.x * BH + bh;
    if (tid == 0)
        s_last = (atomicAdd(&g_cnt[slot], 1u) == NSPLIT - 1) ? 1u : 0u;
    __syncthreads();
    if (!s_last) return;
    __threadfence();                       // acquire other splits' partials

    // merge 128 rows x 64 cols (fixed split order -> deterministic fp sum)
    const int bb = bh / HEADS;
    const int h  = bh % HEADS;
    for (int it = tid; it < 128 * 16; it += 256) {
        const int rloc = it >> 4;
        const int c4   = it & 15;
        const int sabs = q0 + rloc;
        const size_t rowb = (size_t)bh * SEQ + sabs;

        float mm[NSPLIT], ll[NSPLIT];
        float M = -INFINITY;
#pragma unroll
        for (int i = 0; i < NSPLIT; i++) {
            mm[i] = g_Mp[(size_t)i * BHS + rowb];
            ll[i] = g_Lp[(size_t)i * BHS + rowb];
            M = fmaxf(M, mm[i]);
        }
        float w[NSPLIT], denom = 0.f;
#pragma unroll
        for (int i = 0; i < NSPLIT; i++) {
            w[i] = __expf(mm[i] - M);
            denom += ll[i] * w[i];
        }
        float inv = 1.f / denom;
#pragma unroll
        for (int i = 0; i < NSPLIT; i++) w[i] *= inv;

        float v0 = 0.f, v1 = 0.f, v2 = 0.f, v3 = 0.f;
#pragma unroll
        for (int i = 0; i < NSPLIT; i++) {
            float4 a = *(const float4*)&g_Op[((size_t)i * BHS + rowb) * HDIM + c4 * 4];
            v0 += a.x * w[i];
            v1 += a.y * w[i];
            v2 += a.z * w[i];
            v3 += a.w * w[i];
        }

        const size_t dst = ((size_t)(bb * SEQ + sabs)) * EMBED + h * HDIM + c4 * 4;
        float x0, x1, x2, x3;
        unsigned h0 = pack_hi_res(v0, v1, x0, x1);
        unsigned h1 = pack_hi_res(v2, v3, x2, x3);
        *(unsigned*)&Ahi[dst]     = h0;
        *(unsigned*)&Ahi[dst + 2] = h1;
        *(unsigned*)&Alo[dst]     = pack_bf2(x0, x1);
        *(unsigned*)&Alo[dst + 2] = pack_bf2(x2, x3);
    }
    if (tid == 0) g_cnt[slot] = 0;         // reset for next graph replay
}

// ---------------- driver ----------------
extern "C" void kernel_launch(void* const* d_in, const int* in_sizes, int n_in,
                              void* d_out, int out_size)
{
    const float *x, *w_q, *b_q, *w_k, *b_k, *w_v, *b_v, *w_o, *b_o;
    if (n_in == 9 && in_sizes[0] == EMBED && in_sizes[8] == NX) {
        b_k = (const float*)d_in[0]; b_o = (const float*)d_in[1];
        b_q = (const float*)d_in[2]; b_v = (const float*)d_in[3];
        w_k = (const float*)d_in[4]; w_o = (const float*)d_in[5];
        w_q = (const float*)d_in[6]; w_v = (const float*)d_in[7];
        x   = (const float*)d_in[8];
    } else if (n_in == 9 && in_sizes[0] == NX && in_sizes[2] == NW) {
        x   = (const float*)d_in[0];
        w_q = (const float*)d_in[1]; w_k = (const float*)d_in[2];
        w_v = (const float*)d_in[3]; w_o = (const float*)d_in[4];
        b_q = (const float*)d_in[5]; b_k = (const float*)d_in[6];
        b_v = (const float*)d_in[7]; b_o = (const float*)d_in[8];
    } else {
        x   = (const float*)d_in[0];
        w_q = (const float*)d_in[1]; b_q = (const float*)d_in[2];
        w_k = (const float*)d_in[3]; b_k = (const float*)d_in[4];
        w_v = (const float*)d_in[5]; b_v = (const float*)d_in[6];
        w_o = (const float*)d_in[7]; b_o = (const float*)d_in[8];
    }
    float* out = (float*)d_out;

    __nv_bfloat16 *xh, *xl, *w0h, *w0l, *w1h, *w1l, *w2h, *w2l, *w3h, *w3l;
    __nv_bfloat16 *qh, *ql, *kh, *kl, *vh, *vl, *ah, *al;
    cudaGetSymbolAddress((void**)&xh,  g_Xhi);  cudaGetSymbolAddress((void**)&xl,  g_Xlo);
    cudaGetSymbolAddress((void**)&w0h, g_W0hi); cudaGetSymbolAddress((void**)&w0l, g_W0lo);
    cudaGetSymbolAddress((void**)&w1h, g_W1hi); cudaGetSymbolAddress((void**)&w1l, g_W1lo);
    cudaGetSymbolAddress((void**)&w2h, g_W2hi); cudaGetSymbolAddress((void**)&w2l, g_W2lo);
    cudaGetSymbolAddress((void**)&w3h, g_W3hi); cudaGetSymbolAddress((void**)&w3l, g_W3lo);
    cudaGetSymbolAddress((void**)&qh,  g_Qh);   cudaGetSymbolAddress((void**)&ql,  g_Ql);
    cudaGetSymbolAddress((void**)&kh,  g_Kh);   cudaGetSymbolAddress((void**)&kl,  g_Kl);
    cudaGetSymbolAddress((void**)&vh,  g_Vh);   cudaGetSymbolAddress((void**)&vl,  g_Vl);
    cudaGetSymbolAddress((void**)&ah,  g_Ahi);  cudaGetSymbolAddress((void**)&al,  g_Alo);

    cudaFuncSetAttribute(mma_gemm_qkv_kernel,
                         cudaFuncAttributeMaxDynamicSharedMemorySize, SMEM_GEMM_QKV);
    cudaFuncSetAttribute(mma_gemm_o_kernel,
                         cudaFuncAttributeMaxDynamicSharedMemorySize, SMEM_GEMM_O);
    cudaFuncSetAttribute(flash_mma_kernel,
                         cudaFuncAttributeMaxDynamicSharedMemorySize, SMEM_FLASH);

    convert_all_kernel<<<(CONV_TASKS + 255) / 256, 256>>>(
        x, w_q, w_k, w_v, w_o,
        xh, xl, w0h, w0l, w1h, w1l, w2h, w2l, w3h, w3l);

    dim3 qkvgrid(3 * QKV_NBLK, MROWS / GBM);        // (18, 32)
    mma_gemm_qkv_kernel<<<qkvgrid, 256, SMEM_GEMM_QKV>>>(
        xh, xl, w0h, w0l, w1h, w1l, w2h, w2l,
        b_q, b_k, b_v, qh, ql, kh, kl, vh, vl);

    dim3 agrid(QBLKS, BH, NSPLIT);                  // (16, 24, 3)
    flash_mma_kernel<<<agrid, 256, SMEM_FLASH>>>(qh, ql, kh, kl, vh, vl, ah, al);

    dim3 ogrid(O_NBLK, MROWS / GBM);                // (12, 32)
    mma_gemm_o_kernel<<<ogrid, 256, SMEM_GEMM_O>>>(ah, al, w3h, w3l, b_o, out);
}

// round 15
// speedup vs baseline: 1.0497x; 1.0497x over previous
#include <cuda_runtime.h>
#include <cuda_bf16.h>
#include <math.h>

#define EMBED 768
#define HEADS 12
#define HDIM  64
#define BATCH 2
#define SEQ   2048
#define MROWS (BATCH * SEQ)      // 4096
#define BH    (BATCH * HEADS)    // 24
#define NX (MROWS * EMBED)
#define NW (EMBED * EMBED)
#define BHS (BH * SEQ)           // 49152
#define NSPLIT 3

// ---------------- scratch ----------------
__device__ __nv_bfloat16 g_Xhi[NX], g_Xlo[NX];
__device__ __nv_bfloat16 g_W0hi[NW], g_W0lo[NW];
__device__ __nv_bfloat16 g_W1hi[NW], g_W1lo[NW];
__device__ __nv_bfloat16 g_W2hi[NW], g_W2lo[NW];
__device__ __nv_bfloat16 g_W3hi[NW], g_W3lo[NW];
__device__ __nv_bfloat16 g_Qh[NX], g_Ql[NX];
__device__ __nv_bfloat16 g_Kh[NX], g_Kl[NX];
__device__ __nv_bfloat16 g_Vh[NX], g_Vl[NX];
__device__ __nv_bfloat16 g_Ahi[NX], g_Alo[NX];
// split-KV partials
__device__ float g_Op[NSPLIT * BHS * HDIM];
__device__ float g_Mp[NSPLIT * BHS];
__device__ float g_Lp[NSPLIT * BHS];

// ---------------- PTX helpers (family-portable sm_80+) ----------------
__device__ __forceinline__ unsigned smem_u32(const void* p) {
    unsigned a;
    asm("{ .reg .u64 t; cvta.to.shared.u64 t, %1; cvt.u32.u64 %0, t; }" : "=r"(a) : "l"(p));
    return a;
}
__device__ __forceinline__ void cp16(unsigned s, const void* g) {
    asm volatile("cp.async.cg.shared.global [%0], [%1], 16;" :: "r"(s), "l"(g));
}
__device__ __forceinline__ void cp_commit() { asm volatile("cp.async.commit_group;" ::: "memory"); }
template <int N> __device__ __forceinline__ void cp_wait() {
    asm volatile("cp.async.wait_group %0;" :: "n"(N) : "memory");
}
__device__ __forceinline__ void ldx4(unsigned* r, unsigned addr) {
    asm volatile("ldmatrix.sync.aligned.m8n8.x4.shared.b16 {%0,%1,%2,%3}, [%4];"
        : "=r"(r[0]), "=r"(r[1]), "=r"(r[2]), "=r"(r[3]) : "r"(addr));
}
__device__ __forceinline__ void ldx4t(unsigned* r, unsigned addr) {
    asm volatile("ldmatrix.sync.aligned.m8n8.x4.trans.shared.b16 {%0,%1,%2,%3}, [%4];"
        : "=r"(r[0]), "=r"(r[1]), "=r"(r[2]), "=r"(r[3]) : "r"(addr));
}
__device__ __forceinline__ void mma16816(float* d, const unsigned* a, const unsigned* b) {
    asm volatile(
        "mma.sync.aligned.m16n8k16.row.col.f32.bf16.bf16.f32 "
        "{%0,%1,%2,%3}, {%4,%5,%6,%7}, {%8,%9}, {%0,%1,%2,%3};"
        : "+f"(d[0]), "+f"(d[1]), "+f"(d[2]), "+f"(d[3])
        : "r"(a[0]), "r"(a[1]), "r"(a[2]), "r"(a[3]), "r"(b[0]), "r"(b[1]));
}
__device__ __forceinline__ unsigned pack_bf2(float a, float b) {
    __nv_bfloat162 t = __float22bfloat162_rn(make_float2(a, b));
    return *(unsigned*)&t;
}
__device__ __forceinline__ unsigned pack_hi_res(float a, float b, float& ra, float& rb) {
    __nv_bfloat162 t = __float22bfloat162_rn(make_float2(a, b));
    ra = a - __bfloat162float(t.x);
    rb = b - __bfloat162float(t.y);
    return *(unsigned*)&t;
}

// ---------------- fused fp32 -> bf16 hi/lo split (all 5 inputs) ----------------
struct alignas(8) B4 { __nv_bfloat16 v[4]; };
#define CONV_TASKS ((NX + 4 * NW) / 8)

__global__ void __launch_bounds__(256)
convert_all_kernel(const float* __restrict__ x,
                   const float* __restrict__ w0, const float* __restrict__ w1,
                   const float* __restrict__ w2, const float* __restrict__ w3,
                   __nv_bfloat16* xh, __nv_bfloat16* xl,
                   __nv_bfloat16* w0h, __nv_bfloat16* w0l,
                   __nv_bfloat16* w1h, __nv_bfloat16* w1l,
                   __nv_bfloat16* w2h, __nv_bfloat16* w2l,
                   __nv_bfloat16* w3h, __nv_bfloat16* w3l)
{
    long long t = (long long)blockIdx.x * 256 + threadIdx.x;
    if (t >= CONV_TASKS) return;
    long long i = t * 8;
    const float* src;
    __nv_bfloat16 *hi, *lo;
    long long off;
    if (i < NX) { src = x; hi = xh; lo = xl; off = i; }
    else {
        long long j = i - NX;
        int w = (int)(j / NW);
        off = j - (long long)w * NW;
        if      (w == 0) { src = w0; hi = w0h; lo = w0l; }
        else if (w == 1) { src = w1; hi = w1h; lo = w1l; }
        else if (w == 2) { src = w2; hi = w2h; lo = w2l; }
        else             { src = w3; hi = w3h; lo = w3l; }
    }
#pragma unroll
    for (int half = 0; half < 2; half++) {
        float4 v = *(const float4*)&src[off + half * 4];
        B4 h, l;
        float f[4] = {v.x, v.y, v.z, v.w};
#pragma unroll
        for (int j = 0; j < 4; j++) {
            h.v[j] = __float2bfloat16(f[j]);
            l.v[j] = __float2bfloat16(f[j] - __bfloat162float(h.v[j]));
        }
        *(B4*)&hi[off + half * 4] = h;
        *(B4*)&lo[off + half * 4] = l;
    }
}

// ---------------- HMMA GEMM body, templated on (BN, BK) (bf16x3) ----------------
#define GBM 128

template <int BN, int BK>
__device__ __forceinline__ void
gemm_body(unsigned sb,
          const __nv_bfloat16* __restrict__ Ahi, const __nv_bfloat16* __restrict__ Alo,
          const __nv_bfloat16* __restrict__ Bhi, const __nv_bfloat16* __restrict__ Blo,
          const float* __restrict__ bias, float* __restrict__ Yf,
          __nv_bfloat16* __restrict__ Yhi, __nv_bfloat16* __restrict__ Ylo,
          int mode, float scale, int m0, int n0)
{
    constexpr int ASTRD = BK * 2 + 16;          // row stride bytes (data + 16B pad)
    constexpr int A_SZB = 128 * ASTRD;
    constexpr int B_SZB = BN * ASTRD;
    constexpr int STAGE = 2 * A_SZB + 2 * B_SZB;
    constexpr int KITERS = EMBED / BK;
    constexpr int NT   = BN / 16;               // n-frags per warp
    constexpr int WNSP = BN / 2;
    constexpr int CPR  = BK / 8;                // 16B chunks per row
    constexpr int NA   = 128 * CPR / 256;       // A chunk-tasks per thread
    constexpr int NB   = BN * CPR / 256;        // B chunk-tasks per thread

    const int tid  = threadIdx.x;
    const int lane = tid & 31;
    const int wid  = tid >> 5;
    const int warpM = wid & 3;
    const int warpN = wid >> 2;

    auto sA_hi = [&](int s) { return sb + s * STAGE; };
    auto sA_lo = [&](int s) { return sb + s * STAGE + A_SZB; };
    auto sB_hi = [&](int s) { return sb + s * STAGE + 2 * A_SZB; };
    auto sB_lo = [&](int s) { return sb + s * STAGE + 2 * A_SZB + B_SZB; };

    auto load_stage = [&](int kt, int s) {
        const int k0 = kt * BK;
        const __nv_bfloat16* pah = Ahi + (size_t)m0 * EMBED + k0;
        const __nv_bfloat16* pal = Alo + (size_t)m0 * EMBED + k0;
        const __nv_bfloat16* pbh = Bhi + (size_t)n0 * EMBED + k0;
        const __nv_bfloat16* pbl = Blo + (size_t)n0 * EMBED + k0;
#pragma unroll
        for (int i = 0; i < NA; i++) {
            int task = i * 256 + tid;
            int r = task / CPR, c = task % CPR;
            unsigned so = r * ASTRD + c * 16;
            const char* gh = (const char*)(pah + (size_t)r * EMBED) + c * 16;
            const char* gl = (const char*)(pal + (size_t)r * EMBED) + c * 16;
            cp16(sA_hi(s) + so, gh);
            cp16(sA_lo(s) + so, gl);
        }
#pragma unroll
        for (int i = 0; i < NB; i++) {
            int task = i * 256 + tid;
            int r = task / CPR, c = task % CPR;
            unsigned so = r * ASTRD + c * 16;
            const char* gh = (const char*)(pbh + (size_t)r * EMBED) + c * 16;
            const char* gl = (const char*)(pbl + (size_t)r * EMBED) + c * 16;
            cp16(sB_hi(s) + so, gh);
            cp16(sB_lo(s) + so, gl);
        }
        cp_commit();
    };

    const unsigned aOff = (unsigned)((warpM * 32 + ((lane >> 3) & 1) * 8 + (lane & 7)) * ASTRD
                                     + (lane >> 4) * 16);
    const unsigned bOff = (unsigned)((warpN * WNSP + ((lane >> 4) & 1) * 8 + (lane & 7)) * ASTRD
                                     + ((lane >> 3) & 1) * 16);

    float acc[2][NT][4];
#pragma unroll
    for (int mt = 0; mt < 2; mt++)
#pragma unroll
        for (int nt = 0; nt < NT; nt++)
#pragma unroll
            for (int j = 0; j < 4; j++) acc[mt][nt][j] = 0.f;

    load_stage(0, 0);

    for (int kt = 0; kt < KITERS; kt++) {
        const int s = kt & 1;
        cp_wait<0>();
        __syncthreads();
        if (kt + 1 < KITERS) load_stage(kt + 1, s ^ 1);

#pragma unroll
        for (int ks = 0; ks < BK / 16; ks++) {
            unsigned a_h[2][4], a_l[2][4];
#pragma unroll
            for (int mt = 0; mt < 2; mt++) {
                ldx4(a_h[mt], sA_hi(s) + aOff + mt * (16 * ASTRD) + ks * 32);
                ldx4(a_l[mt], sA_lo(s) + aOff + mt * (16 * ASTRD) + ks * 32);
            }
#pragma unroll
            for (int p = 0; p < NT / 2; p++) {
                unsigned b_h[4], b_l[4];
                ldx4(b_h, sB_hi(s) + bOff + p * (16 * ASTRD) + ks * 32);
                ldx4(b_l, sB_lo(s) + bOff + p * (16 * ASTRD) + ks * 32);
#pragma unroll
                for (int mt = 0; mt < 2; mt++)
#pragma unroll
                    for (int j = 0; j < 2; j++) {
                        const int nt = p * 2 + j;
                        mma16816(acc[mt][nt], a_h[mt], &b_h[j * 2]);
                        mma16816(acc[mt][nt], a_h[mt], &b_l[j * 2]);
                        mma16816(acc[mt][nt], a_l[mt], &b_h[j * 2]);
                    }
            }
        }
    }

    const int g  = lane >> 2;
    const int tg = lane & 3;
#pragma unroll
    for (int mt = 0; mt < 2; mt++) {
#pragma unroll
        for (int nt = 0; nt < NT; nt++) {
            const int nl = warpN * WNSP + nt * 8 + tg * 2;
            const int n  = n0 + nl;
            float2 bv = *(const float2*)&bias[n];
#pragma unroll
            for (int half = 0; half < 2; half++) {
                const int ml = warpM * 32 + mt * 16 + g + half * 8;
                const int m  = m0 + ml;
                float c0 = acc[mt][nt][half * 2 + 0] + bv.x;
                float c1 = acc[mt][nt][half * 2 + 1] + bv.y;
                if (mode == 0) {
                    const int h = n >> 6;
                    const int bb = m >> 11;
                    const int ss = m & 2047;
                    float v0 = c0 * scale, v1 = c1 * scale;
                    float r0, r1;
                    unsigned hp = pack_hi_res(v0, v1, r0, r1);
                    unsigned lp = pack_bf2(r0, r1);
                    size_t idx = ((size_t)(bb * HEADS + h) * SEQ + ss) * HDIM + (n & 63);
                    *(unsigned*)&Yhi[idx] = hp;
                    *(unsigned*)&Ylo[idx] = lp;
                } else {
                    *(float2*)&Yf[(size_t)m * EMBED + n] = make_float2(c0, c1);
                }
            }
        }
    }
}

// QKV: BN=64, BK=64 (12 k-tiles, halved syncs, doubled prefetch window)
#define QKV_BN 64
#define QKV_BK 64
#define QKV_NBLK (EMBED / QKV_BN)   // 12
#define QKV_ASTR (QKV_BK * 2 + 16)  // 144
#define SMEM_GEMM_QKV (2 * (2 * 128 * QKV_ASTR + 2 * QKV_BN * QKV_ASTR))  // 110592
// O: BN=64, BK=32 (proven 3-CTA config)
#define O_BN 64
#define O_BK 32
#define O_NBLK (EMBED / O_BN)       // 12
#define O_ASTR (O_BK * 2 + 16)      // 80
#define SMEM_GEMM_O (2 * (2 * 128 * O_ASTR + 2 * O_BN * O_ASTR))          // 61440

__global__ void __launch_bounds__(256, 2)
mma_gemm_qkv_kernel(const __nv_bfloat16* __restrict__ xh, const __nv_bfloat16* __restrict__ xl,
                    const __nv_bfloat16* __restrict__ w0h, const __nv_bfloat16* __restrict__ w0l,
                    const __nv_bfloat16* __restrict__ w1h, const __nv_bfloat16* __restrict__ w1l,
                    const __nv_bfloat16* __restrict__ w2h, const __nv_bfloat16* __restrict__ w2l,
                    const float* __restrict__ b_q, const float* __restrict__ b_k,
                    const float* __restrict__ b_v,
                    __nv_bfloat16* qh, __nv_bfloat16* ql,
                    __nv_bfloat16* kh, __nv_bfloat16* kl,
                    __nv_bfloat16* vh, __nv_bfloat16* vl)
{
    extern __shared__ char smraw[];
    const unsigned sb = smem_u32(smraw);
    const int pj   = blockIdx.x / QKV_NBLK;
    const int nblk = blockIdx.x % QKV_NBLK;
    const __nv_bfloat16 *Bh, *Bl;
    const float* bias;
    __nv_bfloat16 *Yh, *Yl;
    float scale;
    if (pj == 0)      { Bh = w0h; Bl = w0l; bias = b_q; Yh = qh; Yl = ql; scale = 0.125f; }
    else if (pj == 1) { Bh = w1h; Bl = w1l; bias = b_k; Yh = kh; Yl = kl; scale = 1.0f; }
    else              { Bh = w2h; Bl = w2l; bias = b_v; Yh = vh; Yl = vl; scale = 1.0f; }
    gemm_body<QKV_BN, QKV_BK>(sb, xh, xl, Bh, Bl, bias, nullptr, Yh, Yl, 0, scale,
                              blockIdx.y * GBM, nblk * QKV_BN);
}

__global__ void __launch_bounds__(256, 3)
mma_gemm_o_kernel(const __nv_bfloat16* __restrict__ ah, const __nv_bfloat16* __restrict__ al,
                  const __nv_bfloat16* __restrict__ w3h, const __nv_bfloat16* __restrict__ w3l,
                  const float* __restrict__ b_o, float* __restrict__ out)
{
    extern __shared__ char smraw[];
    const unsigned sb = smem_u32(smraw);
    gemm_body<O_BN, O_BK>(sb, ah, al, w3h, w3l, b_o, out, nullptr, nullptr, 1, 1.0f,
                          blockIdx.y * GBM, blockIdx.x * O_BN);
}

// ---------------- Flash attention, split-KV x3, single-sync mainloop ----------------
#define QSTR 144
#define F_oQh 0
#define F_oQl 18432
#define KV_BASE 36864
#define KV_STAGE 36864
#define KV_oKh 0
#define KV_oKl 9216
#define KV_oVh 18432
#define KV_oVl 27648
#define SMEM_FLASH (KV_BASE + 2 * KV_STAGE)   // 110592

__global__ void __launch_bounds__(256)
flash_mma_kernel(const __nv_bfloat16* __restrict__ Qh, const __nv_bfloat16* __restrict__ Ql,
                 const __nv_bfloat16* __restrict__ Kh, const __nv_bfloat16* __restrict__ Kl,
                 const __nv_bfloat16* __restrict__ Vh, const __nv_bfloat16* __restrict__ Vl)
{
    extern __shared__ char smf[];
    const unsigned sb = smem_u32(smf);
    const int tid  = threadIdx.x;
    const int lane = tid & 31;
    const int wid  = tid >> 5;
    const int bh   = blockIdx.y;
    const int q0   = blockIdx.x * 128;
    const int split = blockIdx.z;

    const size_t qoff = ((size_t)bh * SEQ + q0) * HDIM;
    const size_t koff = (size_t)bh * SEQ * HDIM;
    const __nv_bfloat16* pQh = Qh + qoff;
    const __nv_bfloat16* pQl = Ql + qoff;
    const __nv_bfloat16* pKh = Kh + koff;
    const __nv_bfloat16* pKl = Kl + koff;
    const __nv_bfloat16* pVh = Vh + koff;
    const __nv_bfloat16* pVl = Vl + koff;

#pragma unroll
    for (int i = 0; i < 4; i++) {
        int task = tid + i * 256;
        int r = task >> 3, c = task & 7;
        cp16(sb + F_oQh + r * QSTR + c * 16, pQh + (size_t)r * HDIM + c * 8);
        cp16(sb + F_oQl + r * QSTR + c * 16, pQl + (size_t)r * HDIM + c * 8);
    }
    cp_commit();

    auto load_kv = [&](int kt, int s) {
        const unsigned st = sb + KV_BASE + s * KV_STAGE;
        const int k0 = kt * 64;
#pragma unroll
        for (int i = 0; i < 2; i++) {
            int task = tid + i * 256;
            int r = task >> 3, c = task & 7;
            size_t go = (size_t)(k0 + r) * HDIM + c * 8;
            unsigned so = r * QSTR + c * 16;
            cp16(st + KV_oKh + so, pKh + go);
            cp16(st + KV_oKl + so, pKl + go);
            cp16(st + KV_oVh + so, pVh + go);
            cp16(st + KV_oVl + so, pVl + go);
        }
        cp_commit();
    };

    const int g  = lane >> 2;
    const int tg = lane & 3;
    const unsigned aAddr = sb + (unsigned)((wid * 16 + ((lane >> 3) & 1) * 8 + (lane & 7)) * QSTR
                                           + (lane >> 4) * 16);
    const unsigned kRel = (unsigned)((((lane >> 4) & 1) * 8 + (lane & 7)) * QSTR
                                     + ((lane >> 3) & 1) * 16);
    const unsigned vRel = (unsigned)((((lane >> 3) & 1) * 8 + (lane & 7)) * QSTR
                                     + (lane >> 4) * 16);

    float m0 = -INFINITY, m1 = -INFINITY, l0 = 0.f, l1 = 0.f;
    float o[8][4];
#pragma unroll
    for (int nf = 0; nf < 8; nf++)
#pragma unroll
        for (int j = 0; j < 4; j++) o[nf][j] = 0.f;

    const int kt0 = split * 11;
    const int kt1 = (split == 2) ? 32 : kt0 + 11;
    load_kv(kt0, 0);

    for (int kt = kt0; kt < kt1; kt++) {
        const int s = (kt - kt0) & 1;
        cp_wait<0>();
        __syncthreads();
        if (kt + 1 < kt1) load_kv(kt + 1, s ^ 1);

        const unsigned stK = sb + KV_BASE + s * KV_STAGE;

        float sc[8][4];
#pragma unroll
        for (int nf = 0; nf < 8; nf++)
#pragma unroll
            for (int j = 0; j < 4; j++) sc[nf][j] = 0.f;

#pragma unroll
        for (int ks = 0; ks < 4; ks++) {
            unsigned qhf[4], qlf[4];
            ldx4(qhf, aAddr + F_oQh + ks * 32);
            ldx4(qlf, aAddr + F_oQl + ks * 32);
#pragma unroll
            for (int p = 0; p < 4; p++) {
                unsigned khf[4], klf[4];
                ldx4(khf, stK + KV_oKh + kRel + p * (16 * QSTR) + ks * 32);
                ldx4(klf, stK + KV_oKl + kRel + p * (16 * QSTR) + ks * 32);
                mma16816(sc[2 * p],     qhf, &khf[0]);
                mma16816(sc[2 * p],     qhf, &klf[0]);
                mma16816(sc[2 * p],     qlf, &khf[0]);
                mma16816(sc[2 * p + 1], qhf, &khf[2]);
                mma16816(sc[2 * p + 1], qhf, &klf[2]);
                mma16816(sc[2 * p + 1], qlf, &khf[2]);
            }
        }

        float pm0 = sc[0][0], pm1 = sc[0][2];
#pragma unroll
        for (int nf = 0; nf < 8; nf++) {
            pm0 = fmaxf(pm0, fmaxf(sc[nf][0], sc[nf][1]));
            pm1 = fmaxf(pm1, fmaxf(sc[nf][2], sc[nf][3]));
        }
        pm0 = fmaxf(pm0, __shfl_xor_sync(0xffffffffu, pm0, 1, 4));
        pm0 = fmaxf(pm0, __shfl_xor_sync(0xffffffffu, pm0, 2, 4));
        pm1 = fmaxf(pm1, __shfl_xor_sync(0xffffffffu, pm1, 1, 4));
        pm1 = fmaxf(pm1, __shfl_xor_sync(0xffffffffu, pm1, 2, 4));
        const float mn0 = fmaxf(m0, pm0);
        const float mn1 = fmaxf(m1, pm1);
        const float al0 = __expf(m0 - mn0);
        const float al1 = __expf(m1 - mn1);
        m0 = mn0; m1 = mn1;
        float ps0 = 0.f, ps1 = 0.f;
#pragma unroll
        for (int nf = 0; nf < 8; nf++) {
            sc[nf][0] = __expf(sc[nf][0] - mn0);
            sc[nf][1] = __expf(sc[nf][1] - mn0);
            sc[nf][2] = __expf(sc[nf][2] - mn1);
            sc[nf][3] = __expf(sc[nf][3] - mn1);
            ps0 += sc[nf][0] + sc[nf][1];
            ps1 += sc[nf][2] + sc[nf][3];
        }
        ps0 += __shfl_xor_sync(0xffffffffu, ps0, 1, 4);
        ps0 += __shfl_xor_sync(0xffffffffu, ps0, 2, 4);
        ps1 += __shfl_xor_sync(0xffffffffu, ps1, 1, 4);
        ps1 += __shfl_xor_sync(0xffffffffu, ps1, 2, 4);
        l0 = l0 * al0 + ps0;
        l1 = l1 * al1 + ps1;
#pragma unroll
        for (int nf = 0; nf < 8; nf++) {
            o[nf][0] *= al0; o[nf][1] *= al0;
            o[nf][2] *= al1; o[nf][3] *= al1;
        }

#pragma unroll
        for (int kb = 0; kb < 4; kb++) {
            float r0, r1, r2, r3, r4, r5, r6, r7;
            unsigned pa_h[4], pa_l[4];
            pa_h[0] = pack_hi_res(sc[2 * kb][0],     sc[2 * kb][1],     r0, r1);
            pa_h[1] = pack_hi_res(sc[2 * kb][2],     sc[2 * kb][3],     r2, r3);
            pa_h[2] = pack_hi_res(sc[2 * kb + 1][0], sc[2 * kb + 1][1], r4, r5);
            pa_h[3] = pack_hi_res(sc[2 * kb + 1][2], sc[2 * kb + 1][3], r6, r7);
            pa_l[0] = pack_bf2(r0, r1);
            pa_l[1] = pack_bf2(r2, r3);
            pa_l[2] = pack_bf2(r4, r5);
            pa_l[3] = pack_bf2(r6, r7);
#pragma unroll
            for (int du = 0; du < 4; du++) {
                unsigned vhf[4], vlf[4];
                ldx4t(vhf, stK + KV_oVh + vRel + kb * (16 * QSTR) + du * 32);
                ldx4t(vlf, stK + KV_oVl + vRel + kb * (16 * QSTR) + du * 32);
                mma16816(o[du * 2],     pa_h, &vhf[0]);
                mma16816(o[du * 2],     pa_h, &vlf[0]);
                mma16816(o[du * 2],     pa_l, &vhf[0]);
                mma16816(o[du * 2 + 1], pa_h, &vhf[2]);
                mma16816(o[du * 2 + 1], pa_h, &vlf[2]);
                mma16816(o[du * 2 + 1], pa_l, &vhf[2]);
            }
        }
    }

    // ---- store unnormalized partials + (m, l) ----
    const int r0 = q0 + wid * 16 + g;
    const size_t prow = (size_t)(split * BH + bh) * SEQ + r0;
    float* Op0 = &g_Op[prow * HDIM];
    float* Op1 = &g_Op[(prow + 8) * HDIM];
#pragma unroll
    for (int nf = 0; nf < 8; nf++) {
        const int e = nf * 8 + tg * 2;
        *(float2*)&Op0[e] = make_float2(o[nf][0], o[nf][1]);
        *(float2*)&Op1[e] = make_float2(o[nf][2], o[nf][3]);
    }
    if (tg == 0) {
        g_Mp[prow] = m0;     g_Lp[prow] = l0;
        g_Mp[prow + 8] = m1; g_Lp[prow + 8] = l1;
    }
}

// ---------------- split-KV merge: combine NSPLIT partials -> bf16 hi/lo A ----------------
__global__ void __launch_bounds__(256)
merge_kernel(__nv_bfloat16* __restrict__ Ahi, __nv_bfloat16* __restrict__ Alo)
{
    int t = blockIdx.x * 256 + threadIdx.x;
    if (t >= BHS * (HDIM / 4)) return;
    const int c4  = t & 15;
    const size_t row = (size_t)(t >> 4);
    const int bh = (int)(row / SEQ);
    const int s  = (int)(row - (size_t)bh * SEQ);

    float mm[NSPLIT], ll[NSPLIT];
    float M = -INFINITY;
#pragma unroll
    for (int i = 0; i < NSPLIT; i++) {
        mm[i] = g_Mp[(size_t)i * BHS + row];
        ll[i] = g_Lp[(size_t)i * BHS + row];
        M = fmaxf(M, mm[i]);
    }
    float w[NSPLIT], denom = 0.f;
#pragma unroll
    for (int i = 0; i < NSPLIT; i++) {
        w[i] = __expf(mm[i] - M);
        denom += ll[i] * w[i];
    }
    float inv = 1.f / denom;
#pragma unroll
    for (int i = 0; i < NSPLIT; i++) w[i] *= inv;

    float r0 = 0.f, r1 = 0.f, r2 = 0.f, r3 = 0.f;
#pragma unroll
    for (int i = 0; i < NSPLIT; i++) {
        float4 a = *(const float4*)&g_Op[((size_t)i * BHS + row) * HDIM + c4 * 4];
        r0 += a.x * w[i];
        r1 += a.y * w[i];
        r2 += a.z * w[i];
        r3 += a.w * w[i];
    }

    const int bb = bh / HEADS;
    const int h  = bh % HEADS;
    const size_t dst = ((size_t)(bb * SEQ + s)) * EMBED + h * HDIM + c4 * 4;
    float x0, x1, x2, x3;
    unsigned h0 = pack_hi_res(r0, r1, x0, x1);
    unsigned h1 = pack_hi_res(r2, r3, x2, x3);
    *(unsigned*)&Ahi[dst]     = h0;
    *(unsigned*)&Ahi[dst + 2] = h1;
    *(unsigned*)&Alo[dst]     = pack_bf2(x0, x1);
    *(unsigned*)&Alo[dst + 2] = pack_bf2(x2, x3);
}

// ---------------- driver ----------------
extern "C" void kernel_launch(void* const* d_in, const int* in_sizes, int n_in,
                              void* d_out, int out_size)
{
    const float *x, *w_q, *b_q, *w_k, *b_k, *w_v, *b_v, *w_o, *b_o;
    if (n_in == 9 && in_sizes[0] == EMBED && in_sizes[8] == NX) {
        b_k = (const float*)d_in[0]; b_o = (const float*)d_in[1];
        b_q = (const float*)d_in[2]; b_v = (const float*)d_in[3];
        w_k = (const float*)d_in[4]; w_o = (const float*)d_in[5];
        w_q = (const float*)d_in[6]; w_v = (const float*)d_in[7];
        x   = (const float*)d_in[8];
    } else if (n_in == 9 && in_sizes[0] == NX && in_sizes[2] == NW) {
        x   = (const float*)d_in[0];
        w_q = (const float*)d_in[1]; w_k = (const float*)d_in[2];
        w_v = (const float*)d_in[3]; w_o = (const float*)d_in[4];
        b_q = (const float*)d_in[5]; b_k = (const float*)d_in[6];
        b_v = (const float*)d_in[7]; b_o = (const float*)d_in[8];
    } else {
        x   = (const float*)d_in[0];
        w_q = (const float*)d_in[1]; b_q = (const float*)d_in[2];
        w_k = (const float*)d_in[3]; b_k = (const float*)d_in[4];
        w_v = (const float*)d_in[5]; b_v = (const float*)d_in[6];
        w_o = (const float*)d_in[7]; b_o = (const float*)d_in[8];
    }
    float* out = (float*)d_out;

    __nv_bfloat16 *xh, *xl, *w0h, *w0l, *w1h, *w1l, *w2h, *w2l, *w3h, *w3l;
    __nv_bfloat16 *qh, *ql, *kh, *kl, *vh, *vl, *ah, *al;
    cudaGetSymbolAddress((void**)&xh,  g_Xhi);  cudaGetSymbolAddress((void**)&xl,  g_Xlo);
    cudaGetSymbolAddress((void**)&w0h, g_W0hi); cudaGetSymbolAddress((void**)&w0l, g_W0lo);
    cudaGetSymbolAddress((void**)&w1h, g_W1hi); cudaGetSymbolAddress((void**)&w1l, g_W1lo);
    cudaGetSymbolAddress((void**)&w2h, g_W2hi); cudaGetSymbolAddress((void**)&w2l, g_W2lo);
    cudaGetSymbolAddress((void**)&w3h, g_W3hi); cudaGetSymbolAddress((void**)&w3l, g_W3lo);
    cudaGetSymbolAddress((void**)&qh,  g_Qh);   cudaGetSymbolAddress((void**)&ql,  g_Ql);
    cudaGetSymbolAddress((void**)&kh,  g_Kh);   cudaGetSymbolAddress((void**)&kl,  g_Kl);
    cudaGetSymbolAddress((void**)&vh,  g_Vh);   cudaGetSymbolAddress((void**)&vl,  g_Vl);
    cudaGetSymbolAddress((void**)&ah,  g_Ahi);  cudaGetSymbolAddress((void**)&al,  g_Alo);

    cudaFuncSetAttribute(mma_gemm_qkv_kernel,
                         cudaFuncAttributeMaxDynamicSharedMemorySize, SMEM_GEMM_QKV);
    cudaFuncSetAttribute(mma_gemm_o_kernel,
                         cudaFuncAttributeMaxDynamicSharedMemorySize, SMEM_GEMM_O);
    cudaFuncSetAttribute(flash_mma_kernel,
                         cudaFuncAttributeMaxDynamicSharedMemorySize, SMEM_FLASH);

    convert_all_kernel<<<(CONV_TASKS + 255) / 256, 256>>>(
        x, w_q, w_k, w_v, w_o,
        xh, xl, w0h, w0l, w1h, w1l, w2h, w2l, w3h, w3l);

    dim3 qkvgrid(3 * QKV_NBLK, MROWS / GBM);        // (36, 32)
    mma_gemm_qkv_kernel<<<qkvgrid, 256, SMEM_GEMM_QKV>>>(
        xh, xl, w0h, w0l, w1h, w1l, w2h, w2l,
        b_q, b_k, b_v, qh, ql, kh, kl, vh, vl);

    dim3 agrid(SEQ / 128, BH, NSPLIT);              // (16, 24, 3)
    flash_mma_kernel<<<agrid, 256, SMEM_FLASH>>>(qh, ql, kh, kl, vh, vl);

    merge_kernel<<<(BHS * (HDIM / 4) + 255) / 256, 256>>>(ah, al);

    dim3 ogrid(O_NBLK, MROWS / GBM);                // (12, 32)
    mma_gemm_o_kernel<<<ogrid, 256, SMEM_GEMM_O>>>(ah, al, w3h, w3l, b_o, out);
}

// round 16
// speedup vs baseline: 1.0606x; 1.0104x over previous
#include <cuda_runtime.h>
#include <cuda_bf16.h>
#include <math.h>

#define EMBED 768
#define HEADS 12
#define HDIM  64
#define BATCH 2
#define SEQ   2048
#define MROWS (BATCH * SEQ)      // 4096
#define BH    (BATCH * HEADS)    // 24
#define NX (MROWS * EMBED)
#define NW (EMBED * EMBED)
#define BHS (BH * SEQ)           // 49152
#define NSPLIT 3

// ---------------- scratch ----------------
__device__ __nv_bfloat16 g_Xhi[NX], g_Xlo[NX];
__device__ __nv_bfloat16 g_W0hi[NW], g_W0lo[NW];
__device__ __nv_bfloat16 g_W1hi[NW], g_W1lo[NW];
__device__ __nv_bfloat16 g_W2hi[NW], g_W2lo[NW];
__device__ __nv_bfloat16 g_W3hi[NW], g_W3lo[NW];
__device__ __nv_bfloat16 g_Qh[NX], g_Ql[NX];
__device__ __nv_bfloat16 g_Kh[NX], g_Kl[NX];
__device__ __nv_bfloat16 g_Vh[NX], g_Vl[NX];
__device__ __nv_bfloat16 g_Ahi[NX], g_Alo[NX];
// split-KV partials
__device__ float g_Op[NSPLIT * BHS * HDIM];
__device__ float g_Mp[NSPLIT * BHS];
__device__ float g_Lp[NSPLIT * BHS];

// ---------------- PTX helpers (family-portable sm_80+) ----------------
__device__ __forceinline__ unsigned smem_u32(const void* p) {
    unsigned a;
    asm("{ .reg .u64 t; cvta.to.shared.u64 t, %1; cvt.u32.u64 %0, t; }" : "=r"(a) : "l"(p));
    return a;
}
__device__ __forceinline__ void cp16(unsigned s, const void* g) {
    asm volatile("cp.async.cg.shared.global [%0], [%1], 16;" :: "r"(s), "l"(g));
}
__device__ __forceinline__ void cp_commit() { asm volatile("cp.async.commit_group;" ::: "memory"); }
template <int N> __device__ __forceinline__ void cp_wait() {
    asm volatile("cp.async.wait_group %0;" :: "n"(N) : "memory");
}
__device__ __forceinline__ void ldx4(unsigned* r, unsigned addr) {
    asm volatile("ldmatrix.sync.aligned.m8n8.x4.shared.b16 {%0,%1,%2,%3}, [%4];"
        : "=r"(r[0]), "=r"(r[1]), "=r"(r[2]), "=r"(r[3]) : "r"(addr));
}
__device__ __forceinline__ void ldx4t(unsigned* r, unsigned addr) {
    asm volatile("ldmatrix.sync.aligned.m8n8.x4.trans.shared.b16 {%0,%1,%2,%3}, [%4];"
        : "=r"(r[0]), "=r"(r[1]), "=r"(r[2]), "=r"(r[3]) : "r"(addr));
}
__device__ __forceinline__ void mma16816(float* d, const unsigned* a, const unsigned* b) {
    asm volatile(
        "mma.sync.aligned.m16n8k16.row.col.f32.bf16.bf16.f32 "
        "{%0,%1,%2,%3}, {%4,%5,%6,%7}, {%8,%9}, {%0,%1,%2,%3};"
        : "+f"(d[0]), "+f"(d[1]), "+f"(d[2]), "+f"(d[3])
        : "r"(a[0]), "r"(a[1]), "r"(a[2]), "r"(a[3]), "r"(b[0]), "r"(b[1]));
}
__device__ __forceinline__ unsigned pack_bf2(float a, float b) {
    __nv_bfloat162 t = __float22bfloat162_rn(make_float2(a, b));
    return *(unsigned*)&t;
}
__device__ __forceinline__ unsigned pack_hi_res(float a, float b, float& ra, float& rb) {
    __nv_bfloat162 t = __float22bfloat162_rn(make_float2(a, b));
    ra = a - __bfloat162float(t.x);
    rb = b - __bfloat162float(t.y);
    return *(unsigned*)&t;
}

// ---------------- fused fp32 -> bf16 hi/lo split (all 5 inputs) ----------------
struct alignas(8) B4 { __nv_bfloat16 v[4]; };
#define CONV_TASKS ((NX + 4 * NW) / 8)

__global__ void __launch_bounds__(256)
convert_all_kernel(const float* __restrict__ x,
                   const float* __restrict__ w0, const float* __restrict__ w1,
                   const float* __restrict__ w2, const float* __restrict__ w3,
                   __nv_bfloat16* xh, __nv_bfloat16* xl,
                   __nv_bfloat16* w0h, __nv_bfloat16* w0l,
                   __nv_bfloat16* w1h, __nv_bfloat16* w1l,
                   __nv_bfloat16* w2h, __nv_bfloat16* w2l,
                   __nv_bfloat16* w3h, __nv_bfloat16* w3l)
{
    long long t = (long long)blockIdx.x * 256 + threadIdx.x;
    if (t >= CONV_TASKS) return;
    long long i = t * 8;
    const float* src;
    __nv_bfloat16 *hi, *lo;
    long long off;
    if (i < NX) { src = x; hi = xh; lo = xl; off = i; }
    else {
        long long j = i - NX;
        int w = (int)(j / NW);
        off = j - (long long)w * NW;
        if      (w == 0) { src = w0; hi = w0h; lo = w0l; }
        else if (w == 1) { src = w1; hi = w1h; lo = w1l; }
        else if (w == 2) { src = w2; hi = w2h; lo = w2l; }
        else             { src = w3; hi = w3h; lo = w3l; }
    }
#pragma unroll
    for (int half = 0; half < 2; half++) {
        float4 v = *(const float4*)&src[off + half * 4];
        B4 h, l;
        float f[4] = {v.x, v.y, v.z, v.w};
#pragma unroll
        for (int j = 0; j < 4; j++) {
            h.v[j] = __float2bfloat16(f[j]);
            l.v[j] = __float2bfloat16(f[j] - __bfloat162float(h.v[j]));
        }
        *(B4*)&hi[off + half * 4] = h;
        *(B4*)&lo[off + half * 4] = l;
    }
}

// ---------------- HMMA GEMM body, templated on (BN, BK) (bf16x3) ----------------
#define GBM 128

template <int BN, int BK>
__device__ __forceinline__ void
gemm_body(unsigned sb,
          const __nv_bfloat16* __restrict__ Ahi, const __nv_bfloat16* __restrict__ Alo,
          const __nv_bfloat16* __restrict__ Bhi, const __nv_bfloat16* __restrict__ Blo,
          const float* __restrict__ bias, float* __restrict__ Yf,
          __nv_bfloat16* __restrict__ Yhi, __nv_bfloat16* __restrict__ Ylo,
          int mode, float scale, int m0, int n0)
{
    constexpr int ASTRD = BK * 2 + 16;          // row stride bytes (data + 16B pad)
    constexpr int A_SZB = 128 * ASTRD;
    constexpr int B_SZB = BN * ASTRD;
    constexpr int STAGE = 2 * A_SZB + 2 * B_SZB;
    constexpr int KITERS = EMBED / BK;
    constexpr int NT   = BN / 16;
    constexpr int WNSP = BN / 2;
    constexpr int CPR  = BK / 8;
    constexpr int NA   = 128 * CPR / 256;
    constexpr int NB   = BN * CPR / 256;

    const int tid  = threadIdx.x;
    const int lane = tid & 31;
    const int wid  = tid >> 5;
    const int warpM = wid & 3;
    const int warpN = wid >> 2;

    auto sA_hi = [&](int s) { return sb + s * STAGE; };
    auto sA_lo = [&](int s) { return sb + s * STAGE + A_SZB; };
    auto sB_hi = [&](int s) { return sb + s * STAGE + 2 * A_SZB; };
    auto sB_lo = [&](int s) { return sb + s * STAGE + 2 * A_SZB + B_SZB; };

    auto load_stage = [&](int kt, int s) {
        const int k0 = kt * BK;
        const __nv_bfloat16* pah = Ahi + (size_t)m0 * EMBED + k0;
        const __nv_bfloat16* pal = Alo + (size_t)m0 * EMBED + k0;
        const __nv_bfloat16* pbh = Bhi + (size_t)n0 * EMBED + k0;
        const __nv_bfloat16* pbl = Blo + (size_t)n0 * EMBED + k0;
#pragma unroll
        for (int i = 0; i < NA; i++) {
            int task = i * 256 + tid;
            int r = task / CPR, c = task % CPR;
            unsigned so = r * ASTRD + c * 16;
            cp16(sA_hi(s) + so, (const char*)(pah + (size_t)r * EMBED) + c * 16);
            cp16(sA_lo(s) + so, (const char*)(pal + (size_t)r * EMBED) + c * 16);
        }
#pragma unroll
        for (int i = 0; i < NB; i++) {
            int task = i * 256 + tid;
            int r = task / CPR, c = task % CPR;
            unsigned so = r * ASTRD + c * 16;
            cp16(sB_hi(s) + so, (const char*)(pbh + (size_t)r * EMBED) + c * 16);
            cp16(sB_lo(s) + so, (const char*)(pbl + (size_t)r * EMBED) + c * 16);
        }
        cp_commit();
    };

    const unsigned aOff = (unsigned)((warpM * 32 + ((lane >> 3) & 1) * 8 + (lane & 7)) * ASTRD
                                     + (lane >> 4) * 16);
    const unsigned bOff = (unsigned)((warpN * WNSP + ((lane >> 4) & 1) * 8 + (lane & 7)) * ASTRD
                                     + ((lane >> 3) & 1) * 16);

    float acc[2][NT][4];
#pragma unroll
    for (int mt = 0; mt < 2; mt++)
#pragma unroll
        for (int nt = 0; nt < NT; nt++)
#pragma unroll
            for (int j = 0; j < 4; j++) acc[mt][nt][j] = 0.f;

    load_stage(0, 0);

    for (int kt = 0; kt < KITERS; kt++) {
        const int s = kt & 1;
        cp_wait<0>();
        __syncthreads();
        if (kt + 1 < KITERS) load_stage(kt + 1, s ^ 1);

#pragma unroll
        for (int ks = 0; ks < BK / 16; ks++) {
            unsigned a_h[2][4], a_l[2][4];
#pragma unroll
            for (int mt = 0; mt < 2; mt++) {
                ldx4(a_h[mt], sA_hi(s) + aOff + mt * (16 * ASTRD) + ks * 32);
                ldx4(a_l[mt], sA_lo(s) + aOff + mt * (16 * ASTRD) + ks * 32);
            }
#pragma unroll
            for (int p = 0; p < NT / 2; p++) {
                unsigned b_h[4], b_l[4];
                ldx4(b_h, sB_hi(s) + bOff + p * (16 * ASTRD) + ks * 32);
                ldx4(b_l, sB_lo(s) + bOff + p * (16 * ASTRD) + ks * 32);
#pragma unroll
                for (int mt = 0; mt < 2; mt++)
#pragma unroll
                    for (int j = 0; j < 2; j++) {
                        const int nt = p * 2 + j;
                        mma16816(acc[mt][nt], a_h[mt], &b_h[j * 2]);
                        mma16816(acc[mt][nt], a_h[mt], &b_l[j * 2]);
                        mma16816(acc[mt][nt], a_l[mt], &b_h[j * 2]);
                    }
            }
        }
    }

    const int g  = lane >> 2;
    const int tg = lane & 3;
#pragma unroll
    for (int mt = 0; mt < 2; mt++) {
#pragma unroll
        for (int nt = 0; nt < NT; nt++) {
            const int nl = warpN * WNSP + nt * 8 + tg * 2;
            const int n  = n0 + nl;
            float2 bv = *(const float2*)&bias[n];
#pragma unroll
            for (int half = 0; half < 2; half++) {
                const int ml = warpM * 32 + mt * 16 + g + half * 8;
                const int m  = m0 + ml;
                float c0 = acc[mt][nt][half * 2 + 0] + bv.x;
                float c1 = acc[mt][nt][half * 2 + 1] + bv.y;
                if (mode == 0) {
                    const int h = n >> 6;
                    const int bb = m >> 11;
                    const int ss = m & 2047;
                    float v0 = c0 * scale, v1 = c1 * scale;
                    float r0, r1;
                    unsigned hp = pack_hi_res(v0, v1, r0, r1);
                    unsigned lp = pack_bf2(r0, r1);
                    size_t idx = ((size_t)(bb * HEADS + h) * SEQ + ss) * HDIM + (n & 63);
                    *(unsigned*)&Yhi[idx] = hp;
                    *(unsigned*)&Ylo[idx] = lp;
                } else {
                    *(float2*)&Yf[(size_t)m * EMBED + n] = make_float2(c0, c1);
                }
            }
        }
    }
}

// QKV: BN=64, BK=64 (12 k-tiles)
#define QKV_BN 64
#define QKV_BK 64
#define QKV_NBLK (EMBED / QKV_BN)   // 12
#define QKV_ASTR (QKV_BK * 2 + 16)  // 144
#define SMEM_GEMM_QKV (2 * (2 * 128 * QKV_ASTR + 2 * QKV_BN * QKV_ASTR))  // 110592
// O: BN=64, BK=64 (this round's experiment: halve O's sync count too)
#define O_BN 64
#define O_BK 64
#define O_NBLK (EMBED / O_BN)       // 12
#define O_ASTR (O_BK * 2 + 16)      // 144
#define SMEM_GEMM_O (2 * (2 * 128 * O_ASTR + 2 * O_BN * O_ASTR))          // 110592

__global__ void __launch_bounds__(256, 2)
mma_gemm_qkv_kernel(const __nv_bfloat16* __restrict__ xh, const __nv_bfloat16* __restrict__ xl,
                    const __nv_bfloat16* __restrict__ w0h, const __nv_bfloat16* __restrict__ w0l,
                    const __nv_bfloat16* __restrict__ w1h, const __nv_bfloat16* __restrict__ w1l,
                    const __nv_bfloat16* __restrict__ w2h, const __nv_bfloat16* __restrict__ w2l,
                    const float* __restrict__ b_q, const float* __restrict__ b_k,
                    const float* __restrict__ b_v,
                    __nv_bfloat16* qh, __nv_bfloat16* ql,
                    __nv_bfloat16* kh, __nv_bfloat16* kl,
                    __nv_bfloat16* vh, __nv_bfloat16* vl)
{
    extern __shared__ char smraw[];
    const unsigned sb = smem_u32(smraw);
    const int pj   = blockIdx.x / QKV_NBLK;
    const int nblk = blockIdx.x % QKV_NBLK;
    const __nv_bfloat16 *Bh, *Bl;
    const float* bias;
    __nv_bfloat16 *Yh, *Yl;
    float scale;
    if (pj == 0)      { Bh = w0h; Bl = w0l; bias = b_q; Yh = qh; Yl = ql; scale = 0.125f; }
    else if (pj == 1) { Bh = w1h; Bl = w1l; bias = b_k; Yh = kh; Yl = kl; scale = 1.0f; }
    else              { Bh = w2h; Bl = w2l; bias = b_v; Yh = vh; Yl = vl; scale = 1.0f; }
    gemm_body<QKV_BN, QKV_BK>(sb, xh, xl, Bh, Bl, bias, nullptr, Yh, Yl, 0, scale,
                              blockIdx.y * GBM, nblk * QKV_BN);
}

__global__ void __launch_bounds__(256, 2)
mma_gemm_o_kernel(const __nv_bfloat16* __restrict__ ah, const __nv_bfloat16* __restrict__ al,
                  const __nv_bfloat16* __restrict__ w3h, const __nv_bfloat16* __restrict__ w3l,
                  const float* __restrict__ b_o, float* __restrict__ out)
{
    extern __shared__ char smraw[];
    const unsigned sb = smem_u32(smraw);
    gemm_body<O_BN, O_BK>(sb, ah, al, w3h, w3l, b_o, out, nullptr, nullptr, 1, 1.0f,
                          blockIdx.y * GBM, blockIdx.x * O_BN);
}

// ---------------- Flash attention, split-KV x3, single-sync mainloop ----------------
#define QSTR 144
#define F_oQh 0
#define F_oQl 18432
#define KV_BASE 36864
#define KV_STAGE 36864
#define KV_oKh 0
#define KV_oKl 9216
#define KV_oVh 18432
#define KV_oVl 27648
#define SMEM_FLASH (KV_BASE + 2 * KV_STAGE)   // 110592

__global__ void __launch_bounds__(256)
flash_mma_kernel(const __nv_bfloat16* __restrict__ Qh, const __nv_bfloat16* __restrict__ Ql,
                 const __nv_bfloat16* __restrict__ Kh, const __nv_bfloat16* __restrict__ Kl,
                 const __nv_bfloat16* __restrict__ Vh, const __nv_bfloat16* __restrict__ Vl)
{
    extern __shared__ char smf[];
    const unsigned sb = smem_u32(smf);
    const int tid  = threadIdx.x;
    const int lane = tid & 31;
    const int wid  = tid >> 5;
    const int bh   = blockIdx.y;
    const int q0   = blockIdx.x * 128;
    const int split = blockIdx.z;

    const size_t qoff = ((size_t)bh * SEQ + q0) * HDIM;
    const size_t koff = (size_t)bh * SEQ * HDIM;
    const __nv_bfloat16* pQh = Qh + qoff;
    const __nv_bfloat16* pQl = Ql + qoff;
    const __nv_bfloat16* pKh = Kh + koff;
    const __nv_bfloat16* pKl = Kl + koff;
    const __nv_bfloat16* pVh = Vh + koff;
    const __nv_bfloat16* pVl = Vl + koff;

#pragma unroll
    for (int i = 0; i < 4; i++) {
        int task = tid + i * 256;
        int r = task >> 3, c = task & 7;
        cp16(sb + F_oQh + r * QSTR + c * 16, pQh + (size_t)r * HDIM + c * 8);
        cp16(sb + F_oQl + r * QSTR + c * 16, pQl + (size_t)r * HDIM + c * 8);
    }
    cp_commit();

    auto load_kv = [&](int kt, int s) {
        const unsigned st = sb + KV_BASE + s * KV_STAGE;
        const int k0 = kt * 64;
#pragma unroll
        for (int i = 0; i < 2; i++) {
            int task = tid + i * 256;
            int r = task >> 3, c = task & 7;
            size_t go = (size_t)(k0 + r) * HDIM + c * 8;
            unsigned so = r * QSTR + c * 16;
            cp16(st + KV_oKh + so, pKh + go);
            cp16(st + KV_oKl + so, pKl + go);
            cp16(st + KV_oVh + so, pVh + go);
            cp16(st + KV_oVl + so, pVl + go);
        }
        cp_commit();
    };

    const int g  = lane >> 2;
    const int tg = lane & 3;
    const unsigned aAddr = sb + (unsigned)((wid * 16 + ((lane >> 3) & 1) * 8 + (lane & 7)) * QSTR
                                           + (lane >> 4) * 16);
    const unsigned kRel = (unsigned)((((lane >> 4) & 1) * 8 + (lane & 7)) * QSTR
                                     + ((lane >> 3) & 1) * 16);
    const unsigned vRel = (unsigned)((((lane >> 3) & 1) * 8 + (lane & 7)) * QSTR
                                     + (lane >> 4) * 16);

    float m0 = -INFINITY, m1 = -INFINITY, l0 = 0.f, l1 = 0.f;
    float o[8][4];
#pragma unroll
    for (int nf = 0; nf < 8; nf++)
#pragma unroll
        for (int j = 0; j < 4; j++) o[nf][j] = 0.f;

    const int kt0 = split * 11;
    const int kt1 = (split == 2) ? 32 : kt0 + 11;
    load_kv(kt0, 0);

    for (int kt = kt0; kt < kt1; kt++) {
        const int s = (kt - kt0) & 1;
        cp_wait<0>();
        __syncthreads();
        if (kt + 1 < kt1) load_kv(kt + 1, s ^ 1);

        const unsigned stK = sb + KV_BASE + s * KV_STAGE;

        float sc[8][4];
#pragma unroll
        for (int nf = 0; nf < 8; nf++)
#pragma unroll
            for (int j = 0; j < 4; j++) sc[nf][j] = 0.f;

#pragma unroll
        for (int ks = 0; ks < 4; ks++) {
            unsigned qhf[4], qlf[4];
            ldx4(qhf, aAddr + F_oQh + ks * 32);
            ldx4(qlf, aAddr + F_oQl + ks * 32);
#pragma unroll
            for (int p = 0; p < 4; p++) {
                unsigned khf[4], klf[4];
                ldx4(khf, stK + KV_oKh + kRel + p * (16 * QSTR) + ks * 32);
                ldx4(klf, stK + KV_oKl + kRel + p * (16 * QSTR) + ks * 32);
                mma16816(sc[2 * p],     qhf, &khf[0]);
                mma16816(sc[2 * p],     qhf, &klf[0]);
                mma16816(sc[2 * p],     qlf, &khf[0]);
                mma16816(sc[2 * p + 1], qhf, &khf[2]);
                mma16816(sc[2 * p + 1], qhf, &klf[2]);
                mma16816(sc[2 * p + 1], qlf, &khf[2]);
            }
        }

        float pm0 = sc[0][0], pm1 = sc[0][2];
#pragma unroll
        for (int nf = 0; nf < 8; nf++) {
            pm0 = fmaxf(pm0, fmaxf(sc[nf][0], sc[nf][1]));
            pm1 = fmaxf(pm1, fmaxf(sc[nf][2], sc[nf][3]));
        }
        pm0 = fmaxf(pm0, __shfl_xor_sync(0xffffffffu, pm0, 1, 4));
        pm0 = fmaxf(pm0, __shfl_xor_sync(0xffffffffu, pm0, 2, 4));
        pm1 = fmaxf(pm1, __shfl_xor_sync(0xffffffffu, pm1, 1, 4));
        pm1 = fmaxf(pm1, __shfl_xor_sync(0xffffffffu, pm1, 2, 4));
        const float mn0 = fmaxf(m0, pm0);
        const float mn1 = fmaxf(m1, pm1);
        const float al0 = __expf(m0 - mn0);
        const float al1 = __expf(m1 - mn1);
        m0 = mn0; m1 = mn1;
        float ps0 = 0.f, ps1 = 0.f;
#pragma unroll
        for (int nf = 0; nf < 8; nf++) {
            sc[nf][0] = __expf(sc[nf][0] - mn0);
            sc[nf][1] = __expf(sc[nf][1] - mn0);
            sc[nf][2] = __expf(sc[nf][2] - mn1);
            sc[nf][3] = __expf(sc[nf][3] - mn1);
            ps0 += sc[nf][0] + sc[nf][1];
            ps1 += sc[nf][2] + sc[nf][3];
        }
        ps0 += __shfl_xor_sync(0xffffffffu, ps0, 1, 4);
        ps0 += __shfl_xor_sync(0xffffffffu, ps0, 2, 4);
        ps1 += __shfl_xor_sync(0xffffffffu, ps1, 1, 4);
        ps1 += __shfl_xor_sync(0xffffffffu, ps1, 2, 4);
        l0 = l0 * al0 + ps0;
        l1 = l1 * al1 + ps1;
#pragma unroll
        for (int nf = 0; nf < 8; nf++) {
            o[nf][0] *= al0; o[nf][1] *= al0;
            o[nf][2] *= al1; o[nf][3] *= al1;
        }

#pragma unroll
        for (int kb = 0; kb < 4; kb++) {
            float r0, r1, r2, r3, r4, r5, r6, r7;
            unsigned pa_h[4], pa_l[4];
            pa_h[0] = pack_hi_res(sc[2 * kb][0],     sc[2 * kb][1],     r0, r1);
            pa_h[1] = pack_hi_res(sc[2 * kb][2],     sc[2 * kb][3],     r2, r3);
            pa_h[2] = pack_hi_res(sc[2 * kb + 1][0], sc[2 * kb + 1][1], r4, r5);
            pa_h[3] = pack_hi_res(sc[2 * kb + 1][2], sc[2 * kb + 1][3], r6, r7);
            pa_l[0] = pack_bf2(r0, r1);
            pa_l[1] = pack_bf2(r2, r3);
            pa_l[2] = pack_bf2(r4, r5);
            pa_l[3] = pack_bf2(r6, r7);
#pragma unroll
            for (int du = 0; du < 4; du++) {
                unsigned vhf[4], vlf[4];
                ldx4t(vhf, stK + KV_oVh + vRel + kb * (16 * QSTR) + du * 32);
                ldx4t(vlf, stK + KV_oVl + vRel + kb * (16 * QSTR) + du * 32);
                mma16816(o[du * 2],     pa_h, &vhf[0]);
                mma16816(o[du * 2],     pa_h, &vlf[0]);
                mma16816(o[du * 2],     pa_l, &vhf[0]);
                mma16816(o[du * 2 + 1], pa_h, &vhf[2]);
                mma16816(o[du * 2 + 1], pa_h, &vlf[2]);
                mma16816(o[du * 2 + 1], pa_l, &vhf[2]);
            }
        }
    }

    // ---- store unnormalized partials + (m, l) ----
    const int r0 = q0 + wid * 16 + g;
    const size_t prow = (size_t)(split * BH + bh) * SEQ + r0;
    float* Op0 = &g_Op[prow * HDIM];
    float* Op1 = &g_Op[(prow + 8) * HDIM];
#pragma unroll
    for (int nf = 0; nf < 8; nf++) {
        const int e = nf * 8 + tg * 2;
        *(float2*)&Op0[e] = make_float2(o[nf][0], o[nf][1]);
        *(float2*)&Op1[e] = make_float2(o[nf][2], o[nf][3]);
    }
    if (tg == 0) {
        g_Mp[prow] = m0;     g_Lp[prow] = l0;
        g_Mp[prow + 8] = m1; g_Lp[prow + 8] = l1;
    }
}

// ---------------- split-KV merge: combine NSPLIT partials -> bf16 hi/lo A ----------------
__global__ void __launch_bounds__(256)
merge_kernel(__nv_bfloat16* __restrict__ Ahi, __nv_bfloat16* __restrict__ Alo)
{
    int t = blockIdx.x * 256 + threadIdx.x;
    if (t >= BHS * (HDIM / 4)) return;
    const int c4  = t & 15;
    const size_t row = (size_t)(t >> 4);
    const int bh = (int)(row / SEQ);
    const int s  = (int)(row - (size_t)bh * SEQ);

    float mm[NSPLIT], ll[NSPLIT];
    float M = -INFINITY;
#pragma unroll
    for (int i = 0; i < NSPLIT; i++) {
        mm[i] = g_Mp[(size_t)i * BHS + row];
        ll[i] = g_Lp[(size_t)i * BHS + row];
        M = fmaxf(M, mm[i]);
    }
    float w[NSPLIT], denom = 0.f;
#pragma unroll
    for (int i = 0; i < NSPLIT; i++) {
        w[i] = __expf(mm[i] - M);
        denom += ll[i] * w[i];
    }
    float inv = 1.f / denom;
#pragma unroll
    for (int i = 0; i < NSPLIT; i++) w[i] *= inv;

    float r0 = 0.f, r1 = 0.f, r2 = 0.f, r3 = 0.f;
#pragma unroll
    for (int i = 0; i < NSPLIT; i++) {
        float4 a = *(const float4*)&g_Op[((size_t)i * BHS + row) * HDIM + c4 * 4];
        r0 += a.x * w[i];
        r1 += a.y * w[i];
        r2 += a.z * w[i];
        r3 += a.w * w[i];
    }

    const int bb = bh / HEADS;
    const int h  = bh % HEADS;
    const size_t dst = ((size_t)(bb * SEQ + s)) * EMBED + h * HDIM + c4 * 4;
    float x0, x1, x2, x3;
    unsigned h0 = pack_hi_res(r0, r1, x0, x1);
    unsigned h1 = pack_hi_res(r2, r3, x2, x3);
    *(unsigned*)&Ahi[dst]     = h0;
    *(unsigned*)&Ahi[dst + 2] = h1;
    *(unsigned*)&Alo[dst]     = pack_bf2(x0, x1);
    *(unsigned*)&Alo[dst + 2] = pack_bf2(x2, x3);
}

// ---------------- driver ----------------
extern "C" void kernel_launch(void* const* d_in, const int* in_sizes, int n_in,
                              void* d_out, int out_size)
{
    const float *x, *w_q, *b_q, *w_k, *b_k, *w_v, *b_v, *w_o, *b_o;
    if (n_in == 9 && in_sizes[0] == EMBED && in_sizes[8] == NX) {
        b_k = (const float*)d_in[0]; b_o = (const float*)d_in[1];
        b_q = (const float*)d_in[2]; b_v = (const float*)d_in[3];
        w_k = (const float*)d_in[4]; w_o = (const float*)d_in[5];
        w_q = (const float*)d_in[6]; w_v = (const float*)d_in[7];
        x   = (const float*)d_in[8];
    } else if (n_in == 9 && in_sizes[0] == NX && in_sizes[2] == NW) {
        x   = (const float*)d_in[0];
        w_q = (const float*)d_in[1]; w_k = (const float*)d_in[2];
        w_v = (const float*)d_in[3]; w_o = (const float*)d_in[4];
        b_q = (const float*)d_in[5]; b_k = (const float*)d_in[6];
        b_v = (const float*)d_in[7]; b_o = (const float*)d_in[8];
    } else {
        x   = (const float*)d_in[0];
        w_q = (const float*)d_in[1]; b_q = (const float*)d_in[2];
        w_k = (const float*)d_in[3]; b_k = (const float*)d_in[4];
        w_v = (const float*)d_in[5]; b_v = (const float*)d_in[6];
        w_o = (const float*)d_in[7]; b_o = (const float*)d_in[8];
    }
    float* out = (float*)d_out;

    __nv_bfloat16 *xh, *xl, *w0h, *w0l, *w1h, *w1l, *w2h, *w2l, *w3h, *w3l;
    __nv_bfloat16 *qh, *ql, *kh, *kl, *vh, *vl, *ah, *al;
    cudaGetSymbolAddress((void**)&xh,  g_Xhi);  cudaGetSymbolAddress((void**)&xl,  g_Xlo);
    cudaGetSymbolAddress((void**)&w0h, g_W0hi); cudaGetSymbolAddress((void**)&w0l, g_W0lo);
    cudaGetSymbolAddress((void**)&w1h, g_W1hi); cudaGetSymbolAddress((void**)&w1l, g_W1lo);
    cudaGetSymbolAddress((void**)&w2h, g_W2hi); cudaGetSymbolAddress((void**)&w2l, g_W2lo);
    cudaGetSymbolAddress((void**)&w3h, g_W3hi); cudaGetSymbolAddress((void**)&w3l, g_W3lo);
    cudaGetSymbolAddress((void**)&qh,  g_Qh);   cudaGetSymbolAddress((void**)&ql,  g_Ql);
    cudaGetSymbolAddress((void**)&kh,  g_Kh);   cudaGetSymbolAddress((void**)&kl,  g_Kl);
    cudaGetSymbolAddress((void**)&vh,  g_Vh);   cudaGetSymbolAddress((void**)&vl,  g_Vl);
    cudaGetSymbolAddress((void**)&ah,  g_Ahi);  cudaGetSymbolAddress((void**)&al,  g_Alo);

    cudaFuncSetAttribute(mma_gemm_qkv_kernel,
                         cudaFuncAttributeMaxDynamicSharedMemorySize, SMEM_GEMM_QKV);
    cudaFuncSetAttribute(mma_gemm_o_kernel,
                         cudaFuncAttributeMaxDynamicSharedMemorySize, SMEM_GEMM_O);
    cudaFuncSetAttribute(flash_mma_kernel,
                         cudaFuncAttributeMaxDynamicSharedMemorySize, SMEM_FLASH);

    convert_all_kernel<<<(CONV_TASKS + 255) / 256, 256>>>(
        x, w_q, w_k, w_v, w_o,
        xh, xl, w0h, w0l, w1h, w1l, w2h, w2l, w3h, w3l);

    dim3 qkvgrid(3 * QKV_NBLK, MROWS / GBM);        // (36, 32)
    mma_gemm_qkv_kernel<<<qkvgrid, 256, SMEM_GEMM_QKV>>>(
        xh, xl, w0h, w0l, w1h, w1l, w2h, w2l,
        b_q, b_k, b_v, qh, ql, kh, kl, vh, vl);

    dim3 agrid(SEQ / 128, BH, NSPLIT);              // (16, 24, 3)
    flash_mma_kernel<<<agrid, 256, SMEM_FLASH>>>(qh, ql, kh, kl, vh, vl);

    merge_kernel<<<(BHS * (HDIM / 4) + 255) / 256, 256>>>(ah, al);

    dim3 ogrid(O_NBLK, MROWS / GBM);                // (12, 32)
    mma_gemm_o_kernel<<<ogrid, 256, SMEM_GEMM_O>>>(ah, al, w3h, w3l, b_o, out);
}